// round 14
// baseline (speedup 1.0000x reference)
#include <cuda_runtime.h>
#include <math.h>
#include <stdint.h>

#define NN 50000
#define NE 640000
#define D 128

// ---------------- scratch (device globals; no cudaMalloc allowed) ----------------
__device__ float g_Qh[NN * D];
__device__ float g_Kh[NN * D];
__device__ float g_Vh[NN * D];
__device__ float g_wV[NN * D];
__device__ float g_z[NN * 8];
__device__ float g_hh[NN * D];
__device__ float g_h2[NN * D];
__device__ float g_ee[NE * D];
__device__ float g_stats[8 * 128];
__device__ float g_bnp[8 * 128];
__device__ float g_tfw[262144];   // tf32 pre-converted weights (+ transposed We/Woe)

// offsets inside g_tfw
#define TQ  0
#define TK  16384
#define TV  32768
#define TE  49152
#define TOH 65536
#define TOE 81920
#define T1H 98304
#define T2H 131072
#define T1E 163840
#define T2E 196608
#define TET 229376    // We transposed (n-major)
#define TOET 245760   // Wo_e transposed (n-major)

// ---------------- tf32 mma helpers ----------------
__device__ __forceinline__ uint32_t f2tf(float x) {
    uint32_t r;
    asm("cvt.rna.tf32.f32 %0, %1;" : "=r"(r) : "f"(x));
    return r;
}
__device__ __forceinline__ float f2tf_f(float x) { return __uint_as_float(f2tf(x)); }

__device__ __forceinline__ void mma8(float c[4], const uint32_t a[4], uint32_t b0, uint32_t b1) {
    asm volatile(
        "mma.sync.aligned.m16n8k8.row.col.f32.tf32.tf32.f32 "
        "{%0,%1,%2,%3}, {%4,%5,%6,%7}, {%8,%9}, {%0,%1,%2,%3};"
        : "+f"(c[0]), "+f"(c[1]), "+f"(c[2]), "+f"(c[3])
        : "r"(a[0]), "r"(a[1]), "r"(a[2]), "r"(a[3]), "r"(b0), "r"(b1));
}

__device__ __forceinline__ void ldsm4(uint32_t r[4], uint32_t addr) {
    asm volatile("ldmatrix.sync.aligned.m8n8.x4.shared.b16 {%0,%1,%2,%3}, [%4];"
                 : "=r"(r[0]), "=r"(r[1]), "=r"(r[2]), "=r"(r[3]) : "r"(addr));
}

__device__ __forceinline__ void red4(float* p, float x, float y, float z, float w) {
    asm volatile("red.global.add.v4.f32 [%0], {%1,%2,%3,%4};"
                 :: "l"(p), "f"(x), "f"(y), "f"(z), "f"(w) : "memory");
}

// ---------------- weight pre-conversion (tf32-rna, once per call) ----------------
__global__ void k_prep(const float* Wq, const float* Wk, const float* Wv, const float* We,
                       const float* Woh, const float* Woe, const float* W1h, const float* W2h,
                       const float* W1e, const float* W2e) {
    int stride = gridDim.x * blockDim.x;
    for (int i = blockIdx.x * blockDim.x + threadIdx.x; i < 229376; i += stride) {
        float v;
        if (i < 16384) v = Wq[i];
        else if (i < 32768) v = Wk[i - 16384];
        else if (i < 49152) v = Wv[i - 32768];
        else if (i < 65536) v = We[i - 49152];
        else if (i < 81920) v = Woh[i - 65536];
        else if (i < 98304) v = Woe[i - 81920];
        else if (i < 131072) v = W1h[i - 98304];
        else if (i < 163840) v = W2h[i - 131072];
        else if (i < 196608) v = W1e[i - 163840];
        else v = W2e[i - 196608];
        g_tfw[i] = f2tf_f(v);
    }
    // transposed copies (n-major) for LDSM B-operands
    for (int j = blockIdx.x * blockDim.x + threadIdx.x; j < 32768; j += stride) {
        int which = j >> 14;          // 0 -> We, 1 -> Woe
        int idx = j & 16383;
        int n = idx >> 7, k = idx & 127;
        const float* Wsrc = which ? Woe : We;
        g_tfw[(which ? TOET : TET) + idx] = f2tf_f(Wsrc[k * 128 + n]);
    }
}

// ---------------- zero accumulators ----------------
__global__ void k_zero() {
    int idx = blockIdx.x * blockDim.x + threadIdx.x;
    int stride = gridDim.x * blockDim.x;
    const int nwv = NN * D, nz = NN * 8, nst = 8 * 128;
    for (int i = idx; i < nwv; i += stride) g_wV[i] = 0.f;
    for (int i = idx; i < nz; i += stride) g_z[i] = 0.f;
    for (int i = idx; i < nst; i += stride) g_stats[i] = 0.f;
}

// ---------------- Q/K/V GEMMs (tf32 mma, 2 CTAs/SM, fragment-direct stores) ----------------
__global__ __launch_bounds__(256, 2) void k_qkv(const float* __restrict__ h) {
    extern __shared__ float sm[];
    float* sA = sm;                 // 128 x 132 (tf32 of h)
    float* sB = sA + 128 * 132;     // 64 x 136 (tf32 weight k-chunk)
    const int tid = threadIdx.x;
    const int lane = tid & 31, wid = tid >> 5;
    const int g = lane >> 2, q = lane & 3;
    const int wm = wid >> 1, wn = wid & 1;
    const int row0 = blockIdx.x * 128;

    for (int i = tid; i < 128 * 32; i += 256) {
        int r = i >> 5, c4 = (i & 31) << 2;
        float4 v = make_float4(0.f, 0.f, 0.f, 0.f);
        if (row0 + r < NN) v = *(const float4*)(h + (row0 + r) * D + c4);
        sA[r * 132 + c4 + 0] = f2tf_f(v.x);
        sA[r * 132 + c4 + 1] = f2tf_f(v.y);
        sA[r * 132 + c4 + 2] = f2tf_f(v.z);
        sA[r * 132 + c4 + 3] = f2tf_f(v.w);
    }

    for (int wsel = 0; wsel < 3; wsel++) {
        const float* W = g_tfw + wsel * 16384;   // TQ, TK, TV
        float* outp = (wsel == 0) ? g_Qh : (wsel == 1) ? g_Kh : g_Vh;

        float acc[2][8][4];
#pragma unroll
        for (int m = 0; m < 2; m++)
#pragma unroll
            for (int n = 0; n < 8; n++)
#pragma unroll
                for (int j = 0; j < 4; j++) acc[m][n][j] = 0.f;

        for (int half = 0; half < 2; half++) {
            __syncthreads();   // previous consumers of sB done
            for (int i = tid; i < 64 * 32; i += 256) {
                int r = i >> 5, c4 = (i & 31) << 2;
                *(float4*)(sB + r * 136 + c4) = *(const float4*)(W + (half * 64 + r) * 128 + c4);
            }
            __syncthreads();

#pragma unroll 2
            for (int k0 = 0; k0 < 64; k0 += 8) {
                int kk = half * 64 + k0;
                uint32_t a[2][4];
#pragma unroll
                for (int m = 0; m < 2; m++) {
                    int rr = wm * 32 + m * 16;
                    a[m][0] = __float_as_uint(sA[(rr + g) * 132 + kk + q]);
                    a[m][1] = __float_as_uint(sA[(rr + g + 8) * 132 + kk + q]);
                    a[m][2] = __float_as_uint(sA[(rr + g) * 132 + kk + q + 4]);
                    a[m][3] = __float_as_uint(sA[(rr + g + 8) * 132 + kk + q + 4]);
                }
#pragma unroll
                for (int n = 0; n < 8; n++) {
                    uint32_t b0 = __float_as_uint(sB[(k0 + q) * 136 + wn * 64 + n * 8 + g]);
                    uint32_t b1 = __float_as_uint(sB[(k0 + q + 4) * 136 + wn * 64 + n * 8 + g]);
                    mma8(acc[0][n], a[0], b0, b1);
                    mma8(acc[1][n], a[1], b0, b1);
                }
            }
        }

        // fragment-direct stores (4-lane groups write contiguous 32B => sector-efficient)
#pragma unroll
        for (int m = 0; m < 2; m++)
#pragma unroll
            for (int n = 0; n < 8; n++) {
                int r0 = wm * 32 + m * 16 + g, r1 = r0 + 8;
                int cc = wn * 64 + n * 8 + 2 * q;
                if (row0 + r0 < NN)
                    *(float2*)(outp + (size_t)(row0 + r0) * 128 + cc) =
                        make_float2(acc[m][n][0], acc[m][n][1]);
                if (row0 + r1 < NN)
                    *(float2*)(outp + (size_t)(row0 + r1) * 128 + cc) =
                        make_float2(acc[m][n][2], acc[m][n][3]);
            }
    }
}

// ---------------- fused edge kernel (tf32 mma, 3 CTAs/SM, LDSM operands) ----------------
__global__ __launch_bounds__(256, 3) void k_edge1(const float* __restrict__ e,
                                                  const int* __restrict__ src,
                                                  const int* __restrict__ dst,
                                                  const float* __restrict__ bo_e) {
    extern __shared__ float sm[];
    float* sES = sm;                   // 64 x 132: e tile (tf32), later score (tf32)
    float* sWT = sES + 64 * 132;       // 128 x 36: transposed weight chunk (n x k32)
    float* swv = sWT + 128 * 36;       // 64 x 8
    float* sCS = swv + 512;            // 128
    float* sCQ = sCS + 128;            // 128
    int* sSrc = (int*)(sCQ + 128);     // 64
    int* sDst = sSrc + 64;             // 64

    const float* tfWeT = g_tfw + TET;
    const float* tfWoeT = g_tfw + TOET;

    const int tid = threadIdx.x;
    const int lane = tid & 31, wid = tid >> 5;
    const int g = lane >> 2, q = lane & 3;
    const int wm = wid >> 2, wn = wid & 3;   // warp tile: 32 rows x 32 cols
    const int nc0 = wn * 32;
    const int row0 = blockIdx.x * 64;

    // LDSM per-lane offsets
    const int aro = (lane & 7) + ((lane >> 3) & 1) * 8;   // row offset within 16-row tile
    const int aco = (lane >> 4) * 4;                      // col offset (0 or 4)
    const int bno = (lane >> 4) * 8 + (lane & 7);         // n offset within 16-n pair
    const int bko = ((lane >> 3) & 1) * 4;                // k offset (0 or 4)
    const uint32_t sES_u = (uint32_t)__cvta_generic_to_shared(sES);
    const uint32_t sWT_u = (uint32_t)__cvta_generic_to_shared(sWT);

    for (int i = tid; i < 64 * 32; i += 256) {
        int r = i >> 5, c4 = (i & 31) << 2;
        float4 v = *(const float4*)(e + (row0 + r) * D + c4);
        sES[r * 132 + c4 + 0] = f2tf_f(v.x);
        sES[r * 132 + c4 + 1] = f2tf_f(v.y);
        sES[r * 132 + c4 + 2] = f2tf_f(v.z);
        sES[r * 132 + c4 + 3] = f2tf_f(v.w);
    }
    if (tid < 64) { sSrc[tid] = src[row0 + tid]; sDst[tid] = dst[row0 + tid]; }
    if (tid < 128) { sCS[tid] = 0.f; sCQ[tid] = 0.f; }
    __syncthreads();

    // GEMM1: P = e @ We  (4 k-chunks of 32; frags stay in registers)
    float c1[2][4][4];
#pragma unroll
    for (int m = 0; m < 2; m++)
#pragma unroll
        for (int n = 0; n < 4; n++)
#pragma unroll
            for (int j = 0; j < 4; j++) c1[m][n][j] = 0.f;

    for (int ch = 0; ch < 4; ch++) {
        if (ch) __syncthreads();
        for (int i = tid; i < 128 * 8; i += 256) {
            int n = i >> 3, k4 = (i & 7) << 2;
            *(float4*)(sWT + n * 36 + k4) = *(const float4*)(tfWeT + n * 128 + ch * 32 + k4);
        }
        __syncthreads();
#pragma unroll
        for (int k0 = 0; k0 < 32; k0 += 8) {
            int kk = ch * 32 + k0;
            uint32_t a[2][4];
#pragma unroll
            for (int m = 0; m < 2; m++)
                ldsm4(a[m], sES_u + (uint32_t)(((wm * 32 + m * 16 + aro) * 132 + kk + aco) * 4));
#pragma unroll
            for (int p = 0; p < 2; p++) {
                uint32_t b[4];
                ldsm4(b, sWT_u + (uint32_t)(((nc0 + p * 16 + bno) * 36 + k0 + bko) * 4));
                mma8(c1[0][2 * p], a[0], b[0], b[1]);
                mma8(c1[1][2 * p], a[1], b[0], b[1]);
                mma8(c1[0][2 * p + 1], a[0], b[2], b[3]);
                mma8(c1[1][2 * p + 1], a[1], b[2], b[3]);
            }
        }
    }
    __syncthreads();   // all GEMM1 reads of sES done (sES now dead -> reuse for score)

    // In-register: score = P * Kh[src] * Qh[dst] / 4; head sums (shfl); exp; z; write score+swv
    {
        int sidx[2][2], didx[2][2];
#pragma unroll
        for (int m = 0; m < 2; m++)
#pragma unroll
            for (int rh = 0; rh < 2; rh++) {
                int row = wm * 32 + m * 16 + g + rh * 8;
                sidx[m][rh] = sSrc[row];
                didx[m][rh] = sDst[row];
            }

        float ph[2][2][2];   // [m][rh][local head]
#pragma unroll
        for (int m = 0; m < 2; m++)
#pragma unroll
            for (int rh = 0; rh < 2; rh++) { ph[m][rh][0] = 0.f; ph[m][rh][1] = 0.f; }

#pragma unroll
        for (int m = 0; m < 2; m++)
#pragma unroll
            for (int n = 0; n < 4; n++) {
                int cc = nc0 + n * 8 + 2 * q;
#pragma unroll
                for (int rh = 0; rh < 2; rh++) {
                    float2 kv = *(const float2*)(g_Kh + (size_t)sidx[m][rh] * 128 + cc);
                    float2 qv = *(const float2*)(g_Qh + (size_t)didx[m][rh] * 128 + cc);
                    float v0 = c1[m][n][2 * rh] * kv.x * qv.x * 0.25f;
                    float v1 = c1[m][n][2 * rh + 1] * kv.y * qv.y * 0.25f;
                    c1[m][n][2 * rh] = v0;
                    c1[m][n][2 * rh + 1] = v1;
                    ph[m][rh][n >> 1] += v0 + v1;
                }
            }
        // reduce over the 4 q-lanes (lanes g*4+q)
#pragma unroll
        for (int m = 0; m < 2; m++)
#pragma unroll
            for (int rh = 0; rh < 2; rh++)
#pragma unroll
                for (int hh = 0; hh < 2; hh++) {
                    float v = ph[m][rh][hh];
                    v += __shfl_xor_sync(0xffffffff, v, 1);
                    v += __shfl_xor_sync(0xffffffff, v, 2);
                    ph[m][rh][hh] = v;
                }
        // write score (tf32) into sES overlay
#pragma unroll
        for (int m = 0; m < 2; m++)
#pragma unroll
            for (int n = 0; n < 4; n++) {
                int cc = nc0 + n * 8 + 2 * q;
#pragma unroll
                for (int rh = 0; rh < 2; rh++) {
                    int row = wm * 32 + m * 16 + g + rh * 8;
                    sES[row * 132 + cc] = f2tf_f(c1[m][n][2 * rh]);
                    sES[row * 132 + cc + 1] = f2tf_f(c1[m][n][2 * rh + 1]);
                }
            }
        // q==0 lane: exp + swv + z atomics
        if (q == 0) {
#pragma unroll
            for (int m = 0; m < 2; m++)
#pragma unroll
                for (int rh = 0; rh < 2; rh++)
#pragma unroll
                    for (int hh = 0; hh < 2; hh++) {
                        int row = wm * 32 + m * 16 + g + rh * 8;
                        int head = wn * 2 + hh;
                        float ssum = fminf(fmaxf(ph[m][rh][hh], -5.f), 5.f);
                        float wv = __expf(ssum);
                        swv[row * 8 + head] = wv;
                        atomicAdd(&g_z[(size_t)didx[m][rh] * 8 + head], wv);
                    }
        }
    }
    __syncthreads();   // score + swv visible

    // GEMM2: ee_pre = score @ Wo_e  (4 k-chunks; wV segment-sum folded into chunk 0)
    float c2[2][4][4];
#pragma unroll
    for (int m = 0; m < 2; m++)
#pragma unroll
        for (int n = 0; n < 4; n++)
#pragma unroll
            for (int j = 0; j < 4; j++) c2[m][n][j] = 0.f;

    for (int ch = 0; ch < 4; ch++) {
        if (ch) __syncthreads();
        for (int i = tid; i < 128 * 8; i += 256) {
            int n = i >> 3, k4 = (i & 7) << 2;
            *(float4*)(sWT + n * 36 + k4) = *(const float4*)(tfWoeT + n * 128 + ch * 32 + k4);
        }
        if (ch == 0) {
            // wV segment-sum (vectorized red)
            for (int idx = tid; idx < 64 * 32; idx += 256) {
                int r = idx >> 5, c4 = (idx & 31) << 2;
                float wgt = swv[r * 8 + (c4 >> 4)];
                float4 vv = *(const float4*)(g_Vh + (size_t)sSrc[r] * 128 + c4);
                red4(&g_wV[(size_t)sDst[r] * 128 + c4], vv.x * wgt, vv.y * wgt, vv.z * wgt, vv.w * wgt);
            }
        }
        __syncthreads();
#pragma unroll
        for (int k0 = 0; k0 < 32; k0 += 8) {
            int kk = ch * 32 + k0;
            uint32_t a[2][4];
#pragma unroll
            for (int m = 0; m < 2; m++)
                ldsm4(a[m], sES_u + (uint32_t)(((wm * 32 + m * 16 + aro) * 132 + kk + aco) * 4));
#pragma unroll
            for (int p = 0; p < 2; p++) {
                uint32_t b[4];
                ldsm4(b, sWT_u + (uint32_t)(((nc0 + p * 16 + bno) * 36 + k0 + bko) * 4));
                mma8(c2[0][2 * p], a[0], b[0], b[1]);
                mma8(c2[1][2 * p], a[1], b[0], b[1]);
                mma8(c2[0][2 * p + 1], a[0], b[2], b[3]);
                mma8(c2[1][2 * p + 1], a[1], b[2], b[3]);
            }
        }
    }

    // fragment-direct epilogue: bias + residual (re-read e) + store + stats
    {
        float csum[8], csq[8];
#pragma unroll
        for (int j = 0; j < 8; j++) { csum[j] = 0.f; csq[j] = 0.f; }
#pragma unroll
        for (int n = 0; n < 4; n++) {
            int cc = nc0 + n * 8 + 2 * q;
            float2 bb = *(const float2*)(bo_e + cc);
#pragma unroll
            for (int m = 0; m < 2; m++)
#pragma unroll
                for (int rh = 0; rh < 2; rh++) {
                    int gr = row0 + wm * 32 + m * 16 + g + rh * 8;
                    float2 ev = *(const float2*)(e + (size_t)gr * D + cc);
                    float o0 = c2[m][n][2 * rh] + bb.x + ev.x;
                    float o1 = c2[m][n][2 * rh + 1] + bb.y + ev.y;
                    *(float2*)(g_ee + (size_t)gr * 128 + cc) = make_float2(o0, o1);
                    csum[n * 2] += o0; csum[n * 2 + 1] += o1;
                    csq[n * 2] += o0 * o0; csq[n * 2 + 1] += o1 * o1;
                }
        }
#pragma unroll
        for (int n = 0; n < 4; n++) {
            int cc = nc0 + n * 8 + 2 * q;
            atomicAdd(&sCS[cc], csum[n * 2]);
            atomicAdd(&sCS[cc + 1], csum[n * 2 + 1]);
            atomicAdd(&sCQ[cc], csq[n * 2]);
            atomicAdd(&sCQ[cc + 1], csq[n * 2 + 1]);
        }
    }
    __syncthreads();
    if (tid < 128) {
        atomicAdd(&g_stats[0 * 128 + tid], sCS[tid]);
        atomicAdd(&g_stats[1 * 128 + tid], sCQ[tid]);
    }
}

// ---------------- node attention output (tf32 mma, 2 CTAs/SM) ----------------
__global__ __launch_bounds__(256, 2) void k_nattn(const float* __restrict__ h,
                                                  const float* __restrict__ bo_h) {
    extern __shared__ float sm[];
    float* sA = sm;                 // 128 x 132 (tf32 h_attn); aliased by sO after mainloop
    float* sB = sA + 128 * 132;     // 64 x 136 (tf32 Wo_h k-chunk)
    float* sCS = sB + 64 * 136;     // 128
    float* sCQ = sCS + 128;         // 128
    float* sO = sA;                 // overlay
    const int tid = threadIdx.x;
    const int lane = tid & 31, wid = tid >> 5;
    const int g = lane >> 2, q = lane & 3;
    const int wm = wid >> 1, wn = wid & 1;
    const int tx = tid & 15, ty = tid >> 4;
    const int row0 = blockIdx.x * 128;

    for (int i = tid; i < 128 * 128; i += 256) {
        int r = i >> 7, c = i & 127;
        int gr = row0 + r;
        float v = 0.f;
        if (gr < NN) {
            float zz = g_z[gr * 8 + (c >> 4)];
            v = g_wV[gr * 128 + c] / (zz + 1e-6f);
        }
        sA[r * 132 + c] = f2tf_f(v);
    }
    if (tid < 128) { sCS[tid] = 0.f; sCQ[tid] = 0.f; }

    float acc[2][8][4];
#pragma unroll
    for (int m = 0; m < 2; m++)
#pragma unroll
        for (int n = 0; n < 8; n++)
#pragma unroll
            for (int j = 0; j < 4; j++) acc[m][n][j] = 0.f;

    for (int half = 0; half < 2; half++) {
        __syncthreads();
        for (int i = tid; i < 64 * 32; i += 256) {
            int r = i >> 5, c4 = (i & 31) << 2;
            *(float4*)(sB + r * 136 + c4) = *(const float4*)(g_tfw + TOH + (half * 64 + r) * 128 + c4);
        }
        __syncthreads();

#pragma unroll 2
        for (int k0 = 0; k0 < 64; k0 += 8) {
            int kk = half * 64 + k0;
            uint32_t a[2][4];
#pragma unroll
            for (int m = 0; m < 2; m++) {
                int rr = wm * 32 + m * 16;
                a[m][0] = __float_as_uint(sA[(rr + g) * 132 + kk + q]);
                a[m][1] = __float_as_uint(sA[(rr + g + 8) * 132 + kk + q]);
                a[m][2] = __float_as_uint(sA[(rr + g) * 132 + kk + q + 4]);
                a[m][3] = __float_as_uint(sA[(rr + g + 8) * 132 + kk + q + 4]);
            }
#pragma unroll
            for (int n = 0; n < 8; n++) {
                uint32_t b0 = __float_as_uint(sB[(k0 + q) * 136 + wn * 64 + n * 8 + g]);
                uint32_t b1 = __float_as_uint(sB[(k0 + q + 4) * 136 + wn * 64 + n * 8 + g]);
                mma8(acc[0][n], a[0], b0, b1);
                mma8(acc[1][n], a[1], b0, b1);
            }
        }
    }
    __syncthreads();   // all warps done reading sA before overlay writes

#pragma unroll
    for (int m = 0; m < 2; m++)
#pragma unroll
        for (int n = 0; n < 8; n++) {
            int r0 = wm * 32 + m * 16 + g, r1 = r0 + 8;
            int cc = wn * 64 + n * 8 + 2 * q;
            sO[r0 * 132 + cc] = acc[m][n][0];
            sO[r0 * 132 + cc + 1] = acc[m][n][1];
            sO[r1 * 132 + cc] = acc[m][n][2];
            sO[r1 * 132 + cc + 1] = acc[m][n][3];
        }
    __syncthreads();

    float4 bb0 = *(const float4*)(bo_h + tx * 8);
    float4 bb1 = *(const float4*)(bo_h + tx * 8 + 4);
    float bias[8] = {bb0.x, bb0.y, bb0.z, bb0.w, bb1.x, bb1.y, bb1.z, bb1.w};
    float csum[8] = {0, 0, 0, 0, 0, 0, 0, 0};
    float csq[8] = {0, 0, 0, 0, 0, 0, 0, 0};
#pragma unroll
    for (int i = 0; i < 8; i++) {
        int r = ty * 8 + i;
        int gr = row0 + r;
        if (gr < NN) {
            float4 r0 = *(const float4*)(h + gr * 128 + tx * 8);
            float4 r1 = *(const float4*)(h + gr * 128 + tx * 8 + 4);
            float hv[8] = {r0.x, r0.y, r0.z, r0.w, r1.x, r1.y, r1.z, r1.w};
            float o[8];
#pragma unroll
            for (int j = 0; j < 8; j++) {
                o[j] = sO[r * 132 + tx * 8 + j] + bias[j] + hv[j];
                csum[j] += o[j];
                csq[j] += o[j] * o[j];
            }
            *(float4*)(g_hh + gr * 128 + tx * 8) = make_float4(o[0], o[1], o[2], o[3]);
            *(float4*)(g_hh + gr * 128 + tx * 8 + 4) = make_float4(o[4], o[5], o[6], o[7]);
        }
    }
#pragma unroll
    for (int j = 0; j < 8; j++) {
        atomicAdd(&sCS[tx * 8 + j], csum[j]);
        atomicAdd(&sCQ[tx * 8 + j], csq[j]);
    }
    __syncthreads();
    if (tid < 128) {
        atomicAdd(&g_stats[2 * 128 + tid], sCS[tid]);
        atomicAdd(&g_stats[3 * 128 + tid], sCQ[tid]);
    }
}

// ---------------- finalize BN stats ----------------
__global__ void k_finalize(int statOff, float cnt, int bnOff) {
    int c = threadIdx.x;  // 128
    float m = g_stats[statOff + c] / cnt;
    float var = g_stats[statOff + 128 + c] / cnt - m * m;
    g_bnp[bnOff + c] = m;
    g_bnp[bnOff + 128 + c] = rsqrtf(var + 1e-5f);
}

// ---------------- fused BN1 + FFN + residual + stats2 (tf32, 128-row, 2 CTAs/SM, LDSM A-side) ----------------
__global__ __launch_bounds__(256, 2) void k_ffn(const float* __restrict__ xin, float* xout,
                                                int bnOff,
                                                const float* __restrict__ gam,
                                                const float* __restrict__ bet,
                                                const float* __restrict__ W1t,   // tf32 128x256
                                                const float* __restrict__ ba,
                                                const float* __restrict__ W2t,   // tf32 256x128
                                                const float* __restrict__ bb2,
                                                int statOff, int nrows) {
    extern __shared__ float sm[];
    float* sX = sm;                      // 128x132 tf32 post-BN; sO overlay at epilogue
    float* sWb = sX + 128 * 132;         // time-shared: W1 chunk 128x40 OR W2 chunk 32x136 (5120 floats)
    float* sY = sWb + 5120;              // 128x36
    float* sCS = sY + 128 * 36;          // 128
    float* sCQ = sCS + 128;              // 128
    float* sO = sX;                      // overlay (sX dead after last GEMM1)

    const int tid = threadIdx.x;
    const int lane = tid & 31, wid = tid >> 5;
    const int g = lane >> 2, q = lane & 3;
    const int wm = wid >> 1, wn = wid & 1;   // GEMM1: 4 m-groups(32r) x 2 n-groups(16c); GEMM2: 32r x 64c
    const int row0 = blockIdx.x * 128;
    const float* mean = g_bnp + bnOff;
    const float* istd = g_bnp + bnOff + 128;

    const int aro = (lane & 7) + ((lane >> 3) & 1) * 8;
    const int aco = (lane >> 4) * 4;
    const uint32_t sX_u = (uint32_t)__cvta_generic_to_shared(sX);
    const uint32_t sY_u = (uint32_t)__cvta_generic_to_shared(sY);

    for (int i = tid; i < 128 * 128; i += 256) {
        int r = i >> 7, c = i & 127;
        int gr = row0 + r;
        float v = 0.f;
        if (gr < nrows) v = (xin[(size_t)gr * 128 + c] - mean[c]) * istd[c] * gam[c] + bet[c];
        sX[r * 132 + c] = f2tf_f(v);
    }
    if (tid < 128) { sCS[tid] = 0.f; sCQ[tid] = 0.f; }

    float accO[2][8][4];   // rows wm*32 + m*16, cols wn*64 + n*8
#pragma unroll
    for (int m = 0; m < 2; m++)
#pragma unroll
        for (int n = 0; n < 8; n++)
#pragma unroll
            for (int j = 0; j < 4; j++) accO[m][n][j] = 0.f;

    for (int ch = 0; ch < 8; ch++) {
        __syncthreads();   // prior GEMM2 done reading sWb(W2)/sY; ch=0: sX fill visible
        // fill W1 chunk: k=0..127 x cols [ch*32, ch*32+32)
        for (int i = tid; i < 128 * 8; i += 256) {
            int r = i >> 3, c4 = (i & 7) << 2;
            *(float4*)(sWb + r * 40 + c4) = *(const float4*)(W1t + r * 256 + ch * 32 + c4);
        }
        __syncthreads();

        // GEMM1: y = relu(sX @ W1chunk + b1)   out 128x32; warp: 32 rows x 16 cols
        float c1[2][2][4];
#pragma unroll
        for (int m = 0; m < 2; m++)
#pragma unroll
            for (int n = 0; n < 2; n++)
#pragma unroll
                for (int j = 0; j < 4; j++) c1[m][n][j] = 0.f;

        const int cn = wn * 16;
#pragma unroll 2
        for (int k0 = 0; k0 < 128; k0 += 8) {
            uint32_t a[2][4];
#pragma unroll
            for (int m = 0; m < 2; m++)
                ldsm4(a[m], sX_u + (uint32_t)(((wm * 32 + m * 16 + aro) * 132 + k0 + aco) * 4));
#pragma unroll
            for (int n = 0; n < 2; n++) {
                uint32_t b0 = __float_as_uint(sWb[(k0 + q) * 40 + cn + n * 8 + g]);
                uint32_t b1 = __float_as_uint(sWb[(k0 + q + 4) * 40 + cn + n * 8 + g]);
                mma8(c1[0][n], a[0], b0, b1);
                mma8(c1[1][n], a[1], b0, b1);
            }
        }
        // bias + relu -> sY (tf32)
#pragma unroll
        for (int m = 0; m < 2; m++)
#pragma unroll
            for (int n = 0; n < 2; n++) {
                int cc = cn + n * 8 + 2 * q;
                float bv0 = ba[ch * 32 + cc], bv1 = ba[ch * 32 + cc + 1];
                int r0 = wm * 32 + m * 16 + g, r1 = r0 + 8;
                sY[r0 * 36 + cc] = f2tf_f(fmaxf(c1[m][n][0] + bv0, 0.f));
                sY[r0 * 36 + cc + 1] = f2tf_f(fmaxf(c1[m][n][1] + bv1, 0.f));
                sY[r1 * 36 + cc] = f2tf_f(fmaxf(c1[m][n][2] + bv0, 0.f));
                sY[r1 * 36 + cc + 1] = f2tf_f(fmaxf(c1[m][n][3] + bv1, 0.f));
            }
        __syncthreads();   // sY visible; all W1 reads done

        // fill W2 chunk (overlay on sWb): k rows [ch*32, ch*32+32) x 128 cols
        for (int i = tid; i < 32 * 32; i += 256) {
            int r = i >> 5, c4 = (i & 31) << 2;
            *(float4*)(sWb + r * 136 + c4) = *(const float4*)(W2t + (ch * 32 + r) * 128 + c4);
        }
        __syncthreads();

        // GEMM2 accumulate: out += y @ W2chunk  (k=32); warp: 32 rows x 64 cols
#pragma unroll
        for (int k0 = 0; k0 < 32; k0 += 8) {
            uint32_t a[2][4];
#pragma unroll
            for (int m = 0; m < 2; m++)
                ldsm4(a[m], sY_u + (uint32_t)(((wm * 32 + m * 16 + aro) * 36 + k0 + aco) * 4));
#pragma unroll
            for (int n = 0; n < 8; n++) {
                uint32_t b0 = __float_as_uint(sWb[(k0 + q) * 136 + wn * 64 + n * 8 + g]);
                uint32_t b1 = __float_as_uint(sWb[(k0 + q + 4) * 136 + wn * 64 + n * 8 + g]);
                mma8(accO[0][n], a[0], b0, b1);
                mma8(accO[1][n], a[1], b0, b1);
            }
        }
    }
    __syncthreads();   // all reads of sX (GEMM1) and sWb/sY done

    // stage output frags to sO (overlay on sX)
#pragma unroll
    for (int m = 0; m < 2; m++)
#pragma unroll
        for (int n = 0; n < 8; n++) {
            int r0 = wm * 32 + m * 16 + g, r1 = r0 + 8;
            int cc = wn * 64 + n * 8 + 2 * q;
            sO[r0 * 132 + cc] = accO[m][n][0];
            sO[r0 * 132 + cc + 1] = accO[m][n][1];
            sO[r1 * 132 + cc] = accO[m][n][2];
            sO[r1 * 132 + cc + 1] = accO[m][n][3];
        }
    __syncthreads();

    // epilogue: bias + residual (recompute BN fp32 from re-read xin) + store + stats
    const int tx = tid & 15, ty = tid >> 4;
    float4 c0 = *(const float4*)(bb2 + tx * 8);
    float4 c1v = *(const float4*)(bb2 + tx * 8 + 4);
    float bias[8] = {c0.x, c0.y, c0.z, c0.w, c1v.x, c1v.y, c1v.z, c1v.w};
    float mn[8], is_[8], gm[8], bt[8];
#pragma unroll
    for (int j = 0; j < 8; j++) {
        int c = tx * 8 + j;
        mn[j] = mean[c]; is_[j] = istd[c]; gm[j] = gam[c]; bt[j] = bet[c];
    }
    float csum[8] = {0, 0, 0, 0, 0, 0, 0, 0};
    float csq[8] = {0, 0, 0, 0, 0, 0, 0, 0};
#pragma unroll
    for (int i = 0; i < 8; i++) {
        int r = ty * 8 + i;
        int gr = row0 + r;
        if (gr < nrows) {
            float4 x0 = *(const float4*)(xin + (size_t)gr * 128 + tx * 8);
            float4 x1 = *(const float4*)(xin + (size_t)gr * 128 + tx * 8 + 4);
            float xv[8] = {x0.x, x0.y, x0.z, x0.w, x1.x, x1.y, x1.z, x1.w};
            float o[8];
#pragma unroll
            for (int j = 0; j < 8; j++) {
                float resid = (xv[j] - mn[j]) * is_[j] * gm[j] + bt[j];
                o[j] = sO[r * 132 + tx * 8 + j] + bias[j] + resid;
                csum[j] += o[j];
                csq[j] += o[j] * o[j];
            }
            *(float4*)(xout + (size_t)gr * 128 + tx * 8) = make_float4(o[0], o[1], o[2], o[3]);
            *(float4*)(xout + (size_t)gr * 128 + tx * 8 + 4) = make_float4(o[4], o[5], o[6], o[7]);
        }
    }
#pragma unroll
    for (int j = 0; j < 8; j++) {
        atomicAdd(&sCS[tx * 8 + j], csum[j]);
        atomicAdd(&sCQ[tx * 8 + j], csq[j]);
    }
    __syncthreads();
    if (tid < 128) {
        atomicAdd(&g_stats[statOff + tid], sCS[tid]);
        atomicAdd(&g_stats[statOff + 128 + tid], sCQ[tid]);
    }
}

// ---------------- final BN (elementwise) ----------------
__global__ void k_bnout(const float* x, int bnOff, const float* gam, const float* bet,
                        float* o, int nrows) {
    const float* mean = g_bnp + bnOff;
    const float* istd = g_bnp + bnOff + 128;
    int idx = blockIdx.x * blockDim.x + threadIdx.x;
    int stride = gridDim.x * blockDim.x;
    int total = nrows * 32;  // float4 units
    for (int i = idx; i < total; i += stride) {
        int c = (i & 31) << 2;
        float4 v = *(const float4*)(x + (size_t)i * 4);
        float4 r;
        r.x = (v.x - mean[c + 0]) * istd[c + 0] * gam[c + 0] + bet[c + 0];
        r.y = (v.y - mean[c + 1]) * istd[c + 1] * gam[c + 1] + bet[c + 1];
        r.z = (v.z - mean[c + 2]) * istd[c + 2] * gam[c + 2] + bet[c + 2];
        r.w = (v.w - mean[c + 3]) * istd[c + 3] * gam[c + 3] + bet[c + 3];
        *(float4*)(o + (size_t)i * 4) = r;
    }
}

// ---------------- launch ----------------
extern "C" void kernel_launch(void* const* d_in, const int* in_sizes, int n_in,
                              void* d_out, int out_size) {
    const float* h = (const float*)d_in[0];
    const float* e = (const float*)d_in[1];
    const int* src = (const int*)d_in[2];
    const int* dst = (const int*)d_in[3];
    const float* Wq = (const float*)d_in[4];
    const float* Wk = (const float*)d_in[5];
    const float* Wv = (const float*)d_in[6];
    const float* We = (const float*)d_in[7];
    const float* Wo_h = (const float*)d_in[8];
    const float* bo_h = (const float*)d_in[9];
    const float* Wo_e = (const float*)d_in[10];
    const float* bo_e = (const float*)d_in[11];
    const float* g1h = (const float*)d_in[12];
    const float* b1h = (const float*)d_in[13];
    const float* g1e = (const float*)d_in[14];
    const float* b1e = (const float*)d_in[15];
    const float* Wf1h = (const float*)d_in[16];
    const float* bf1h = (const float*)d_in[17];
    const float* Wf2h = (const float*)d_in[18];
    const float* bf2h = (const float*)d_in[19];
    const float* Wf1e = (const float*)d_in[20];
    const float* bf1e = (const float*)d_in[21];
    const float* Wf2e = (const float*)d_in[22];
    const float* bf2e = (const float*)d_in[23];
    const float* g2h = (const float*)d_in[24];
    const float* b2h = (const float*)d_in[25];
    const float* g2e = (const float*)d_in[26];
    const float* b2e = (const float*)d_in[27];
    float* out = (float*)d_out;
    float* out_e = out + (size_t)NN * D;

    float *p_hh, *p_h2, *p_ee, *p_tfw;
    cudaGetSymbolAddress((void**)&p_hh, g_hh);
    cudaGetSymbolAddress((void**)&p_h2, g_h2);
    cudaGetSymbolAddress((void**)&p_ee, g_ee);
    cudaGetSymbolAddress((void**)&p_tfw, g_tfw);

    const int smQ = (128 * 132 + 64 * 136) * 4;                              // ~100KB
    const int smN = (128 * 132 + 64 * 136 + 256) * 4;                        // ~101KB
    const int sm1 = (64 * 132 + 128 * 36 + 512 + 256 + 128) * 4;             // ~55.8KB
    const int smF = (128 * 132 + 5120 + 128 * 36 + 256) * 4;                 // 105KB
    cudaFuncSetAttribute(k_qkv, cudaFuncAttributeMaxDynamicSharedMemorySize, smQ);
    cudaFuncSetAttribute(k_nattn, cudaFuncAttributeMaxDynamicSharedMemorySize, smN);
    cudaFuncSetAttribute(k_edge1, cudaFuncAttributeMaxDynamicSharedMemorySize, sm1);
    cudaFuncSetAttribute(k_ffn, cudaFuncAttributeMaxDynamicSharedMemorySize, smF);

    const int NBLK = (NN + 127) / 128;  // 391

    k_zero<<<2048, 256>>>();
    k_prep<<<256, 256>>>(Wq, Wk, Wv, We, Wo_h, Wo_e, Wf1h, Wf2h, Wf1e, Wf2e);
    k_qkv<<<NBLK, 256, smQ>>>(h);
    k_edge1<<<NE / 64, 256, sm1>>>(e, src, dst, bo_e);
    k_nattn<<<NBLK, 256, smN>>>(h, bo_h);
    k_finalize<<<1, 128>>>(0, (float)NE, 0);      // bn1e
    k_finalize<<<1, 128>>>(256, (float)NN, 256);  // bn1h
    k_ffn<<<NE / 128, 256, smF>>>(p_ee, out_e, 0, g1e, b1e, p_tfw + T1E, bf1e, p_tfw + T2E, bf2e, 512, NE);
    k_ffn<<<NBLK, 256, smF>>>(p_hh, p_h2, 256, g1h, b1h, p_tfw + T1H, bf1h, p_tfw + T2H, bf2h, 768, NN);
    k_finalize<<<1, 128>>>(512, (float)NE, 512);  // bn2e
    k_finalize<<<1, 128>>>(768, (float)NN, 768);  // bn2h
    k_bnout<<<2960, 256>>>(p_h2, 768, g2h, b2h, out, NN);
    k_bnout<<<2960, 256>>>(out_e, 512, g2e, b2e, out_e, NE);
}

// round 15
// speedup vs baseline: 1.0469x; 1.0469x over previous
#include <cuda_runtime.h>
#include <math.h>
#include <stdint.h>

#define NN 50000
#define NE 640000
#define D 128

// ---------------- scratch (device globals; no cudaMalloc allowed) ----------------
__device__ float g_Qh[NN * D];
__device__ float g_Kh[NN * D];
__device__ float g_Vh[NN * D];
__device__ float g_wV[NN * D];
__device__ float g_z[NN * 8];
__device__ float g_hh[NN * D];
__device__ float g_h2[NN * D];
__device__ float g_ee[NE * D];
__device__ float g_stats[8 * 128];
__device__ float g_bnp[8 * 128];
__device__ float g_tfw[229376];   // tf32 pre-converted weights

// offsets inside g_tfw
#define TQ  0
#define TK  16384
#define TV  32768
#define TE  49152
#define TOH 65536
#define TOE 81920
#define T1H 98304
#define T2H 131072
#define T1E 163840
#define T2E 196608

// ---------------- tf32 mma helpers ----------------
__device__ __forceinline__ uint32_t f2tf(float x) {
    uint32_t r;
    asm("cvt.rna.tf32.f32 %0, %1;" : "=r"(r) : "f"(x));
    return r;
}
__device__ __forceinline__ float f2tf_f(float x) { return __uint_as_float(f2tf(x)); }

__device__ __forceinline__ void mma8(float c[4], const uint32_t a[4], uint32_t b0, uint32_t b1) {
    asm volatile(
        "mma.sync.aligned.m16n8k8.row.col.f32.tf32.tf32.f32 "
        "{%0,%1,%2,%3}, {%4,%5,%6,%7}, {%8,%9}, {%0,%1,%2,%3};"
        : "+f"(c[0]), "+f"(c[1]), "+f"(c[2]), "+f"(c[3])
        : "r"(a[0]), "r"(a[1]), "r"(a[2]), "r"(a[3]), "r"(b0), "r"(b1));
}

__device__ __forceinline__ void red4(float* p, float x, float y, float z, float w) {
    asm volatile("red.global.add.v4.f32 [%0], {%1,%2,%3,%4};"
                 :: "l"(p), "f"(x), "f"(y), "f"(z), "f"(w) : "memory");
}

// ---------------- weight pre-conversion (tf32-rna, once per call) ----------------
__global__ void k_prep(const float* Wq, const float* Wk, const float* Wv, const float* We,
                       const float* Woh, const float* Woe, const float* W1h, const float* W2h,
                       const float* W1e, const float* W2e) {
    int i = blockIdx.x * blockDim.x + threadIdx.x;
    int stride = gridDim.x * blockDim.x;
    for (; i < 229376; i += stride) {
        float v;
        if (i < 16384) v = Wq[i];
        else if (i < 32768) v = Wk[i - 16384];
        else if (i < 49152) v = Wv[i - 32768];
        else if (i < 65536) v = We[i - 49152];
        else if (i < 81920) v = Woh[i - 65536];
        else if (i < 98304) v = Woe[i - 81920];
        else if (i < 131072) v = W1h[i - 98304];
        else if (i < 163840) v = W2h[i - 131072];
        else if (i < 196608) v = W1e[i - 163840];
        else v = W2e[i - 196608];
        g_tfw[i] = f2tf_f(v);
    }
}

// ---------------- zero accumulators ----------------
__global__ void k_zero() {
    int idx = blockIdx.x * blockDim.x + threadIdx.x;
    int stride = gridDim.x * blockDim.x;
    const int nwv = NN * D, nz = NN * 8, nst = 8 * 128;
    for (int i = idx; i < nwv; i += stride) g_wV[i] = 0.f;
    for (int i = idx; i < nz; i += stride) g_z[i] = 0.f;
    for (int i = idx; i < nst; i += stride) g_stats[i] = 0.f;
}

// ---------------- Q/K/V GEMMs (tf32 mma, 2 CTAs/SM, fragment-direct stores) ----------------
__global__ __launch_bounds__(256, 2) void k_qkv(const float* __restrict__ h) {
    extern __shared__ float sm[];
    float* sA = sm;                 // 128 x 132 (tf32 of h)
    float* sB = sA + 128 * 132;     // 64 x 136 (tf32 weight k-chunk)
    const int tid = threadIdx.x;
    const int lane = tid & 31, wid = tid >> 5;
    const int g = lane >> 2, q = lane & 3;
    const int wm = wid >> 1, wn = wid & 1;
    const int row0 = blockIdx.x * 128;

    for (int i = tid; i < 128 * 32; i += 256) {
        int r = i >> 5, c4 = (i & 31) << 2;
        float4 v = make_float4(0.f, 0.f, 0.f, 0.f);
        if (row0 + r < NN) v = *(const float4*)(h + (row0 + r) * D + c4);
        sA[r * 132 + c4 + 0] = f2tf_f(v.x);
        sA[r * 132 + c4 + 1] = f2tf_f(v.y);
        sA[r * 132 + c4 + 2] = f2tf_f(v.z);
        sA[r * 132 + c4 + 3] = f2tf_f(v.w);
    }

    for (int wsel = 0; wsel < 3; wsel++) {
        const float* W = g_tfw + wsel * 16384;   // TQ, TK, TV
        float* outp = (wsel == 0) ? g_Qh : (wsel == 1) ? g_Kh : g_Vh;

        float acc[2][8][4];
#pragma unroll
        for (int m = 0; m < 2; m++)
#pragma unroll
            for (int n = 0; n < 8; n++)
#pragma unroll
                for (int j = 0; j < 4; j++) acc[m][n][j] = 0.f;

        for (int half = 0; half < 2; half++) {
            __syncthreads();   // previous consumers of sB done
            for (int i = tid; i < 64 * 32; i += 256) {
                int r = i >> 5, c4 = (i & 31) << 2;
                *(float4*)(sB + r * 136 + c4) = *(const float4*)(W + (half * 64 + r) * 128 + c4);
            }
            __syncthreads();

#pragma unroll 2
            for (int k0 = 0; k0 < 64; k0 += 8) {
                int kk = half * 64 + k0;
                uint32_t a[2][4];
#pragma unroll
                for (int m = 0; m < 2; m++) {
                    int rr = wm * 32 + m * 16;
                    a[m][0] = __float_as_uint(sA[(rr + g) * 132 + kk + q]);
                    a[m][1] = __float_as_uint(sA[(rr + g + 8) * 132 + kk + q]);
                    a[m][2] = __float_as_uint(sA[(rr + g) * 132 + kk + q + 4]);
                    a[m][3] = __float_as_uint(sA[(rr + g + 8) * 132 + kk + q + 4]);
                }
#pragma unroll
                for (int n = 0; n < 8; n++) {
                    uint32_t b0 = __float_as_uint(sB[(k0 + q) * 136 + wn * 64 + n * 8 + g]);
                    uint32_t b1 = __float_as_uint(sB[(k0 + q + 4) * 136 + wn * 64 + n * 8 + g]);
                    mma8(acc[0][n], a[0], b0, b1);
                    mma8(acc[1][n], a[1], b0, b1);
                }
            }
        }

        // fragment-direct stores (4-lane groups write contiguous 32B => sector-efficient)
#pragma unroll
        for (int m = 0; m < 2; m++)
#pragma unroll
            for (int n = 0; n < 8; n++) {
                int r0 = wm * 32 + m * 16 + g, r1 = r0 + 8;
                int cc = wn * 64 + n * 8 + 2 * q;
                if (row0 + r0 < NN)
                    *(float2*)(outp + (size_t)(row0 + r0) * 128 + cc) =
                        make_float2(acc[m][n][0], acc[m][n][1]);
                if (row0 + r1 < NN)
                    *(float2*)(outp + (size_t)(row0 + r1) * 128 + cc) =
                        make_float2(acc[m][n][2], acc[m][n][3]);
            }
    }
}

// ---------------- fused edge kernel (tf32 mma, 3 CTAs/SM, fragment-resident, 64-row W chunks) ----------------
__global__ __launch_bounds__(256, 3) void k_edge1(const float* __restrict__ e,
                                                  const int* __restrict__ src,
                                                  const int* __restrict__ dst,
                                                  const float* __restrict__ bo_e) {
    extern __shared__ float sm[];
    float* sES = sm;                   // 64 x 132: e tile (tf32), later score (tf32)
    float* sW = sES + 64 * 132;        // 64 x 136 (tf32 weight k-chunk)
    float* swv = sW + 64 * 136;        // 64 x 8
    float* sCS = swv + 512;            // 128
    float* sCQ = sCS + 128;            // 128
    int* sSrc = (int*)(sCQ + 128);     // 64
    int* sDst = sSrc + 64;             // 64

    const float* tfWe = g_tfw + TE;
    const float* tfWoe = g_tfw + TOE;

    const int tid = threadIdx.x;
    const int lane = tid & 31, wid = tid >> 5;
    const int g = lane >> 2, q = lane & 3;
    const int wm = wid >> 2, wn = wid & 3;   // warp tile: 32 rows x 32 cols
    const int nc0 = wn * 32;
    const int row0 = blockIdx.x * 64;

    for (int i = tid; i < 64 * 32; i += 256) {
        int r = i >> 5, c4 = (i & 31) << 2;
        float4 v = *(const float4*)(e + (row0 + r) * D + c4);
        sES[r * 132 + c4 + 0] = f2tf_f(v.x);
        sES[r * 132 + c4 + 1] = f2tf_f(v.y);
        sES[r * 132 + c4 + 2] = f2tf_f(v.z);
        sES[r * 132 + c4 + 3] = f2tf_f(v.w);
    }
    for (int i = tid; i < 64 * 32; i += 256) {
        int r = i >> 5, c4 = (i & 31) << 2;
        *(float4*)(sW + r * 136 + c4) = *(const float4*)(tfWe + r * 128 + c4);
    }
    if (tid < 64) { sSrc[tid] = src[row0 + tid]; sDst[tid] = dst[row0 + tid]; }
    if (tid < 128) { sCS[tid] = 0.f; sCQ[tid] = 0.f; }
    __syncthreads();

    // GEMM1: P = e @ We  (2 k-halves of 64; frags stay in registers)
    float c1[2][4][4];
#pragma unroll
    for (int m = 0; m < 2; m++)
#pragma unroll
        for (int n = 0; n < 4; n++)
#pragma unroll
            for (int j = 0; j < 4; j++) c1[m][n][j] = 0.f;

    for (int half = 0; half < 2; half++) {
        if (half) {
            __syncthreads();
            for (int i = tid; i < 64 * 32; i += 256) {
                int r = i >> 5, c4 = (i & 31) << 2;
                *(float4*)(sW + r * 136 + c4) = *(const float4*)(tfWe + (64 + r) * 128 + c4);
            }
            __syncthreads();
        }
#pragma unroll 2
        for (int k0 = 0; k0 < 64; k0 += 8) {
            int kk = half * 64 + k0;
            uint32_t a[2][4];
#pragma unroll
            for (int m = 0; m < 2; m++) {
                int rr = wm * 32 + m * 16;
                a[m][0] = __float_as_uint(sES[(rr + g) * 132 + kk + q]);
                a[m][1] = __float_as_uint(sES[(rr + g + 8) * 132 + kk + q]);
                a[m][2] = __float_as_uint(sES[(rr + g) * 132 + kk + q + 4]);
                a[m][3] = __float_as_uint(sES[(rr + g + 8) * 132 + kk + q + 4]);
            }
#pragma unroll
            for (int n = 0; n < 4; n++) {
                uint32_t b0 = __float_as_uint(sW[(k0 + q) * 136 + nc0 + n * 8 + g]);
                uint32_t b1 = __float_as_uint(sW[(k0 + q + 4) * 136 + nc0 + n * 8 + g]);
                mma8(c1[0][n], a[0], b0, b1);
                mma8(c1[1][n], a[1], b0, b1);
            }
        }
    }
    __syncthreads();   // all GEMM1 reads of sES done (sES now dead -> reuse for score)

    // In-register: score = P * Kh[src] * Qh[dst] / 4; head sums (shfl); exp; z; write score+swv
    {
        int sidx[2][2], didx[2][2];
#pragma unroll
        for (int m = 0; m < 2; m++)
#pragma unroll
            for (int rh = 0; rh < 2; rh++) {
                int row = wm * 32 + m * 16 + g + rh * 8;
                sidx[m][rh] = sSrc[row];
                didx[m][rh] = sDst[row];
            }

        float ph[2][2][2];   // [m][rh][local head]
#pragma unroll
        for (int m = 0; m < 2; m++)
#pragma unroll
            for (int rh = 0; rh < 2; rh++) { ph[m][rh][0] = 0.f; ph[m][rh][1] = 0.f; }

#pragma unroll
        for (int m = 0; m < 2; m++)
#pragma unroll
            for (int n = 0; n < 4; n++) {
                int cc = nc0 + n * 8 + 2 * q;
#pragma unroll
                for (int rh = 0; rh < 2; rh++) {
                    float2 kv = *(const float2*)(g_Kh + (size_t)sidx[m][rh] * 128 + cc);
                    float2 qv = *(const float2*)(g_Qh + (size_t)didx[m][rh] * 128 + cc);
                    float v0 = c1[m][n][2 * rh] * kv.x * qv.x * 0.25f;
                    float v1 = c1[m][n][2 * rh + 1] * kv.y * qv.y * 0.25f;
                    c1[m][n][2 * rh] = v0;
                    c1[m][n][2 * rh + 1] = v1;
                    ph[m][rh][n >> 1] += v0 + v1;
                }
            }
        // reduce over the 4 q-lanes (lanes g*4+q)
#pragma unroll
        for (int m = 0; m < 2; m++)
#pragma unroll
            for (int rh = 0; rh < 2; rh++)
#pragma unroll
                for (int hh = 0; hh < 2; hh++) {
                    float v = ph[m][rh][hh];
                    v += __shfl_xor_sync(0xffffffff, v, 1);
                    v += __shfl_xor_sync(0xffffffff, v, 2);
                    ph[m][rh][hh] = v;
                }
        // write score (tf32) into sES overlay
#pragma unroll
        for (int m = 0; m < 2; m++)
#pragma unroll
            for (int n = 0; n < 4; n++) {
                int cc = nc0 + n * 8 + 2 * q;
#pragma unroll
                for (int rh = 0; rh < 2; rh++) {
                    int row = wm * 32 + m * 16 + g + rh * 8;
                    sES[row * 132 + cc] = f2tf_f(c1[m][n][2 * rh]);
                    sES[row * 132 + cc + 1] = f2tf_f(c1[m][n][2 * rh + 1]);
                }
            }
        // q==0 lane: exp + swv + z atomics
        if (q == 0) {
#pragma unroll
            for (int m = 0; m < 2; m++)
#pragma unroll
                for (int rh = 0; rh < 2; rh++)
#pragma unroll
                    for (int hh = 0; hh < 2; hh++) {
                        int row = wm * 32 + m * 16 + g + rh * 8;
                        int head = wn * 2 + hh;
                        float ssum = fminf(fmaxf(ph[m][rh][hh], -5.f), 5.f);
                        float wv = __expf(ssum);
                        swv[row * 8 + head] = wv;
                        atomicAdd(&g_z[(size_t)didx[m][rh] * 8 + head], wv);
                    }
        }
    }
    __syncthreads();   // score + swv visible

    // GEMM2: ee_pre = score @ Wo_e  (2 k-halves; wV segment-sum folded into half 0)
    float c2[2][4][4];
#pragma unroll
    for (int m = 0; m < 2; m++)
#pragma unroll
        for (int n = 0; n < 4; n++)
#pragma unroll
            for (int j = 0; j < 4; j++) c2[m][n][j] = 0.f;

    for (int half = 0; half < 2; half++) {
        if (half) __syncthreads();
        for (int i = tid; i < 64 * 32; i += 256) {
            int r = i >> 5, c4 = (i & 31) << 2;
            *(float4*)(sW + r * 136 + c4) = *(const float4*)(tfWoe + (half * 64 + r) * 128 + c4);
        }
        if (half == 0) {
            // wV segment-sum (vectorized red)
            for (int idx = tid; idx < 64 * 32; idx += 256) {
                int r = idx >> 5, c4 = (idx & 31) << 2;
                float wgt = swv[r * 8 + (c4 >> 4)];
                float4 vv = *(const float4*)(g_Vh + (size_t)sSrc[r] * 128 + c4);
                red4(&g_wV[(size_t)sDst[r] * 128 + c4], vv.x * wgt, vv.y * wgt, vv.z * wgt, vv.w * wgt);
            }
        }
        __syncthreads();
#pragma unroll 2
        for (int k0 = 0; k0 < 64; k0 += 8) {
            int kk = half * 64 + k0;
            uint32_t a[2][4];
#pragma unroll
            for (int m = 0; m < 2; m++) {
                int rr = wm * 32 + m * 16;
                a[m][0] = __float_as_uint(sES[(rr + g) * 132 + kk + q]);
                a[m][1] = __float_as_uint(sES[(rr + g + 8) * 132 + kk + q]);
                a[m][2] = __float_as_uint(sES[(rr + g) * 132 + kk + q + 4]);
                a[m][3] = __float_as_uint(sES[(rr + g + 8) * 132 + kk + q + 4]);
            }
#pragma unroll
            for (int n = 0; n < 4; n++) {
                uint32_t b0 = __float_as_uint(sW[(k0 + q) * 136 + nc0 + n * 8 + g]);
                uint32_t b1 = __float_as_uint(sW[(k0 + q + 4) * 136 + nc0 + n * 8 + g]);
                mma8(c2[0][n], a[0], b0, b1);
                mma8(c2[1][n], a[1], b0, b1);
            }
        }
    }

    // fragment-direct epilogue: bias + residual (re-read e) + store + stats
    {
        float csum[8], csq[8];
#pragma unroll
        for (int j = 0; j < 8; j++) { csum[j] = 0.f; csq[j] = 0.f; }
#pragma unroll
        for (int n = 0; n < 4; n++) {
            int cc = nc0 + n * 8 + 2 * q;
            float2 bb = *(const float2*)(bo_e + cc);
#pragma unroll
            for (int m = 0; m < 2; m++)
#pragma unroll
                for (int rh = 0; rh < 2; rh++) {
                    int gr = row0 + wm * 32 + m * 16 + g + rh * 8;
                    float2 ev = *(const float2*)(e + (size_t)gr * D + cc);
                    float o0 = c2[m][n][2 * rh] + bb.x + ev.x;
                    float o1 = c2[m][n][2 * rh + 1] + bb.y + ev.y;
                    *(float2*)(g_ee + (size_t)gr * 128 + cc) = make_float2(o0, o1);
                    csum[n * 2] += o0; csum[n * 2 + 1] += o1;
                    csq[n * 2] += o0 * o0; csq[n * 2 + 1] += o1 * o1;
                }
        }
#pragma unroll
        for (int n = 0; n < 4; n++) {
            int cc = nc0 + n * 8 + 2 * q;
            atomicAdd(&sCS[cc], csum[n * 2]);
            atomicAdd(&sCS[cc + 1], csum[n * 2 + 1]);
            atomicAdd(&sCQ[cc], csq[n * 2]);
            atomicAdd(&sCQ[cc + 1], csq[n * 2 + 1]);
        }
    }
    __syncthreads();
    if (tid < 128) {
        atomicAdd(&g_stats[0 * 128 + tid], sCS[tid]);
        atomicAdd(&g_stats[1 * 128 + tid], sCQ[tid]);
    }
}

// ---------------- node attention output (tf32 mma, 2 CTAs/SM) ----------------
__global__ __launch_bounds__(256, 2) void k_nattn(const float* __restrict__ h,
                                                  const float* __restrict__ bo_h) {
    extern __shared__ float sm[];
    float* sA = sm;                 // 128 x 132 (tf32 h_attn); aliased by sO after mainloop
    float* sB = sA + 128 * 132;     // 64 x 136 (tf32 Wo_h k-chunk)
    float* sCS = sB + 64 * 136;     // 128
    float* sCQ = sCS + 128;         // 128
    float* sO = sA;                 // overlay
    const int tid = threadIdx.x;
    const int lane = tid & 31, wid = tid >> 5;
    const int g = lane >> 2, q = lane & 3;
    const int wm = wid >> 1, wn = wid & 1;
    const int tx = tid & 15, ty = tid >> 4;
    const int row0 = blockIdx.x * 128;

    for (int i = tid; i < 128 * 128; i += 256) {
        int r = i >> 7, c = i & 127;
        int gr = row0 + r;
        float v = 0.f;
        if (gr < NN) {
            float zz = g_z[gr * 8 + (c >> 4)];
            v = g_wV[gr * 128 + c] / (zz + 1e-6f);
        }
        sA[r * 132 + c] = f2tf_f(v);
    }
    if (tid < 128) { sCS[tid] = 0.f; sCQ[tid] = 0.f; }

    float acc[2][8][4];
#pragma unroll
    for (int m = 0; m < 2; m++)
#pragma unroll
        for (int n = 0; n < 8; n++)
#pragma unroll
            for (int j = 0; j < 4; j++) acc[m][n][j] = 0.f;

    for (int half = 0; half < 2; half++) {
        __syncthreads();
        for (int i = tid; i < 64 * 32; i += 256) {
            int r = i >> 5, c4 = (i & 31) << 2;
            *(float4*)(sB + r * 136 + c4) = *(const float4*)(g_tfw + TOH + (half * 64 + r) * 128 + c4);
        }
        __syncthreads();

#pragma unroll 2
        for (int k0 = 0; k0 < 64; k0 += 8) {
            int kk = half * 64 + k0;
            uint32_t a[2][4];
#pragma unroll
            for (int m = 0; m < 2; m++) {
                int rr = wm * 32 + m * 16;
                a[m][0] = __float_as_uint(sA[(rr + g) * 132 + kk + q]);
                a[m][1] = __float_as_uint(sA[(rr + g + 8) * 132 + kk + q]);
                a[m][2] = __float_as_uint(sA[(rr + g) * 132 + kk + q + 4]);
                a[m][3] = __float_as_uint(sA[(rr + g + 8) * 132 + kk + q + 4]);
            }
#pragma unroll
            for (int n = 0; n < 8; n++) {
                uint32_t b0 = __float_as_uint(sB[(k0 + q) * 136 + wn * 64 + n * 8 + g]);
                uint32_t b1 = __float_as_uint(sB[(k0 + q + 4) * 136 + wn * 64 + n * 8 + g]);
                mma8(acc[0][n], a[0], b0, b1);
                mma8(acc[1][n], a[1], b0, b1);
            }
        }
    }
    __syncthreads();   // all warps done reading sA before overlay writes

#pragma unroll
    for (int m = 0; m < 2; m++)
#pragma unroll
        for (int n = 0; n < 8; n++) {
            int r0 = wm * 32 + m * 16 + g, r1 = r0 + 8;
            int cc = wn * 64 + n * 8 + 2 * q;
            sO[r0 * 132 + cc] = acc[m][n][0];
            sO[r0 * 132 + cc + 1] = acc[m][n][1];
            sO[r1 * 132 + cc] = acc[m][n][2];
            sO[r1 * 132 + cc + 1] = acc[m][n][3];
        }
    __syncthreads();

    float4 bb0 = *(const float4*)(bo_h + tx * 8);
    float4 bb1 = *(const float4*)(bo_h + tx * 8 + 4);
    float bias[8] = {bb0.x, bb0.y, bb0.z, bb0.w, bb1.x, bb1.y, bb1.z, bb1.w};
    float csum[8] = {0, 0, 0, 0, 0, 0, 0, 0};
    float csq[8] = {0, 0, 0, 0, 0, 0, 0, 0};
#pragma unroll
    for (int i = 0; i < 8; i++) {
        int r = ty * 8 + i;
        int gr = row0 + r;
        if (gr < NN) {
            float4 r0 = *(const float4*)(h + gr * 128 + tx * 8);
            float4 r1 = *(const float4*)(h + gr * 128 + tx * 8 + 4);
            float hv[8] = {r0.x, r0.y, r0.z, r0.w, r1.x, r1.y, r1.z, r1.w};
            float o[8];
#pragma unroll
            for (int j = 0; j < 8; j++) {
                o[j] = sO[r * 132 + tx * 8 + j] + bias[j] + hv[j];
                csum[j] += o[j];
                csq[j] += o[j] * o[j];
            }
            *(float4*)(g_hh + gr * 128 + tx * 8) = make_float4(o[0], o[1], o[2], o[3]);
            *(float4*)(g_hh + gr * 128 + tx * 8 + 4) = make_float4(o[4], o[5], o[6], o[7]);
        }
    }
#pragma unroll
    for (int j = 0; j < 8; j++) {
        atomicAdd(&sCS[tx * 8 + j], csum[j]);
        atomicAdd(&sCQ[tx * 8 + j], csq[j]);
    }
    __syncthreads();
    if (tid < 128) {
        atomicAdd(&g_stats[2 * 128 + tid], sCS[tid]);
        atomicAdd(&g_stats[3 * 128 + tid], sCQ[tid]);
    }
}

// ---------------- finalize BN stats ----------------
__global__ void k_finalize(int statOff, float cnt, int bnOff) {
    int c = threadIdx.x;  // 128
    float m = g_stats[statOff + c] / cnt;
    float var = g_stats[statOff + 128 + c] / cnt - m * m;
    g_bnp[bnOff + c] = m;
    g_bnp[bnOff + 128 + c] = rsqrtf(var + 1e-5f);
}

// ---------------- fused BN1 + FFN + residual + stats2 (tf32, 128-row, 2 CTAs/SM via W buffer time-share) ----------------
__global__ __launch_bounds__(256, 2) void k_ffn(const float* __restrict__ xin, float* xout,
                                                int bnOff,
                                                const float* __restrict__ gam,
                                                const float* __restrict__ bet,
                                                const float* __restrict__ W1t,   // tf32 128x256
                                                const float* __restrict__ ba,
                                                const float* __restrict__ W2t,   // tf32 256x128
                                                const float* __restrict__ bb2,
                                                int statOff, int nrows) {
    extern __shared__ float sm[];
    float* sX = sm;                      // 128x132 tf32 post-BN; sO overlay at epilogue
    float* sWb = sX + 128 * 132;         // time-shared: W1 chunk 128x40 OR W2 chunk 32x136 (5120 floats)
    float* sY = sWb + 5120;              // 128x36
    float* sCS = sY + 128 * 36;          // 128
    float* sCQ = sCS + 128;              // 128
    float* sO = sX;                      // overlay (sX dead after last GEMM1)

    const int tid = threadIdx.x;
    const int lane = tid & 31, wid = tid >> 5;
    const int g = lane >> 2, q = lane & 3;
    const int wm = wid >> 1, wn = wid & 1;   // GEMM1: 4 m-groups(32r) x 2 n-groups(16c); GEMM2: 32r x 64c
    const int row0 = blockIdx.x * 128;
    const float* mean = g_bnp + bnOff;
    const float* istd = g_bnp + bnOff + 128;

    for (int i = tid; i < 128 * 128; i += 256) {
        int r = i >> 7, c = i & 127;
        int gr = row0 + r;
        float v = 0.f;
        if (gr < nrows) v = (xin[(size_t)gr * 128 + c] - mean[c]) * istd[c] * gam[c] + bet[c];
        sX[r * 132 + c] = f2tf_f(v);
    }
    if (tid < 128) { sCS[tid] = 0.f; sCQ[tid] = 0.f; }

    float accO[2][8][4];   // rows wm*32 + m*16, cols wn*64 + n*8
#pragma unroll
    for (int m = 0; m < 2; m++)
#pragma unroll
        for (int n = 0; n < 8; n++)
#pragma unroll
            for (int j = 0; j < 4; j++) accO[m][n][j] = 0.f;

    for (int ch = 0; ch < 8; ch++) {
        __syncthreads();   // prior GEMM2 done reading sWb(W2)/sY; ch=0: sX fill visible
        // fill W1 chunk: k=0..127 x cols [ch*32, ch*32+32)
        for (int i = tid; i < 128 * 8; i += 256) {
            int r = i >> 3, c4 = (i & 7) << 2;
            *(float4*)(sWb + r * 40 + c4) = *(const float4*)(W1t + r * 256 + ch * 32 + c4);
        }
        __syncthreads();

        // GEMM1: y = relu(sX @ W1chunk + b1)   out 128x32; warp: 32 rows x 16 cols
        float c1[2][2][4];
#pragma unroll
        for (int m = 0; m < 2; m++)
#pragma unroll
            for (int n = 0; n < 2; n++)
#pragma unroll
                for (int j = 0; j < 4; j++) c1[m][n][j] = 0.f;

        const int cn = wn * 16;
#pragma unroll 2
        for (int k0 = 0; k0 < 128; k0 += 8) {
            uint32_t a[2][4];
#pragma unroll
            for (int m = 0; m < 2; m++) {
                int rr = wm * 32 + m * 16;
                a[m][0] = __float_as_uint(sX[(rr + g) * 132 + k0 + q]);
                a[m][1] = __float_as_uint(sX[(rr + g + 8) * 132 + k0 + q]);
                a[m][2] = __float_as_uint(sX[(rr + g) * 132 + k0 + q + 4]);
                a[m][3] = __float_as_uint(sX[(rr + g + 8) * 132 + k0 + q + 4]);
            }
#pragma unroll
            for (int n = 0; n < 2; n++) {
                uint32_t b0 = __float_as_uint(sWb[(k0 + q) * 40 + cn + n * 8 + g]);
                uint32_t b1 = __float_as_uint(sWb[(k0 + q + 4) * 40 + cn + n * 8 + g]);
                mma8(c1[0][n], a[0], b0, b1);
                mma8(c1[1][n], a[1], b0, b1);
            }
        }
        // bias + relu -> sY (tf32)
#pragma unroll
        for (int m = 0; m < 2; m++)
#pragma unroll
            for (int n = 0; n < 2; n++) {
                int cc = cn + n * 8 + 2 * q;
                float bv0 = ba[ch * 32 + cc], bv1 = ba[ch * 32 + cc + 1];
                int r0 = wm * 32 + m * 16 + g, r1 = r0 + 8;
                sY[r0 * 36 + cc] = f2tf_f(fmaxf(c1[m][n][0] + bv0, 0.f));
                sY[r0 * 36 + cc + 1] = f2tf_f(fmaxf(c1[m][n][1] + bv1, 0.f));
                sY[r1 * 36 + cc] = f2tf_f(fmaxf(c1[m][n][2] + bv0, 0.f));
                sY[r1 * 36 + cc + 1] = f2tf_f(fmaxf(c1[m][n][3] + bv1, 0.f));
            }
        __syncthreads();   // sY visible; all W1 reads done

        // fill W2 chunk (overlay on sWb): k rows [ch*32, ch*32+32) x 128 cols
        for (int i = tid; i < 32 * 32; i += 256) {
            int r = i >> 5, c4 = (i & 31) << 2;
            *(float4*)(sWb + r * 136 + c4) = *(const float4*)(W2t + (ch * 32 + r) * 128 + c4);
        }
        __syncthreads();

        // GEMM2 accumulate: out += y @ W2chunk  (k=32); warp: 32 rows x 64 cols
#pragma unroll
        for (int k0 = 0; k0 < 32; k0 += 8) {
            uint32_t a[2][4];
#pragma unroll
            for (int m = 0; m < 2; m++) {
                int rr = wm * 32 + m * 16;
                a[m][0] = __float_as_uint(sY[(rr + g) * 36 + k0 + q]);
                a[m][1] = __float_as_uint(sY[(rr + g + 8) * 36 + k0 + q]);
                a[m][2] = __float_as_uint(sY[(rr + g) * 36 + k0 + q + 4]);
                a[m][3] = __float_as_uint(sY[(rr + g + 8) * 36 + k0 + q + 4]);
            }
#pragma unroll
            for (int n = 0; n < 8; n++) {
                uint32_t b0 = __float_as_uint(sWb[(k0 + q) * 136 + wn * 64 + n * 8 + g]);
                uint32_t b1 = __float_as_uint(sWb[(k0 + q + 4) * 136 + wn * 64 + n * 8 + g]);
                mma8(accO[0][n], a[0], b0, b1);
                mma8(accO[1][n], a[1], b0, b1);
            }
        }
    }
    __syncthreads();   // all reads of sX (GEMM1) and sWb/sY done

    // stage output frags to sO (overlay on sX)
#pragma unroll
    for (int m = 0; m < 2; m++)
#pragma unroll
        for (int n = 0; n < 8; n++) {
            int r0 = wm * 32 + m * 16 + g, r1 = r0 + 8;
            int cc = wn * 64 + n * 8 + 2 * q;
            sO[r0 * 132 + cc] = accO[m][n][0];
            sO[r0 * 132 + cc + 1] = accO[m][n][1];
            sO[r1 * 132 + cc] = accO[m][n][2];
            sO[r1 * 132 + cc + 1] = accO[m][n][3];
        }
    __syncthreads();

    // epilogue: bias + residual (recompute BN fp32 from re-read xin) + store + stats
    const int tx = tid & 15, ty = tid >> 4;
    float4 c0 = *(const float4*)(bb2 + tx * 8);
    float4 c1v = *(const float4*)(bb2 + tx * 8 + 4);
    float bias[8] = {c0.x, c0.y, c0.z, c0.w, c1v.x, c1v.y, c1v.z, c1v.w};
    float mn[8], is_[8], gm[8], bt[8];
#pragma unroll
    for (int j = 0; j < 8; j++) {
        int c = tx * 8 + j;
        mn[j] = mean[c]; is_[j] = istd[c]; gm[j] = gam[c]; bt[j] = bet[c];
    }
    float csum[8] = {0, 0, 0, 0, 0, 0, 0, 0};
    float csq[8] = {0, 0, 0, 0, 0, 0, 0, 0};
#pragma unroll
    for (int i = 0; i < 8; i++) {
        int r = ty * 8 + i;
        int gr = row0 + r;
        if (gr < nrows) {
            float4 x0 = *(const float4*)(xin + (size_t)gr * 128 + tx * 8);
            float4 x1 = *(const float4*)(xin + (size_t)gr * 128 + tx * 8 + 4);
            float xv[8] = {x0.x, x0.y, x0.z, x0.w, x1.x, x1.y, x1.z, x1.w};
            float o[8];
#pragma unroll
            for (int j = 0; j < 8; j++) {
                float resid = (xv[j] - mn[j]) * is_[j] * gm[j] + bt[j];
                o[j] = sO[r * 132 + tx * 8 + j] + bias[j] + resid;
                csum[j] += o[j];
                csq[j] += o[j] * o[j];
            }
            *(float4*)(xout + (size_t)gr * 128 + tx * 8) = make_float4(o[0], o[1], o[2], o[3]);
            *(float4*)(xout + (size_t)gr * 128 + tx * 8 + 4) = make_float4(o[4], o[5], o[6], o[7]);
        }
    }
#pragma unroll
    for (int j = 0; j < 8; j++) {
        atomicAdd(&sCS[tx * 8 + j], csum[j]);
        atomicAdd(&sCQ[tx * 8 + j], csq[j]);
    }
    __syncthreads();
    if (tid < 128) {
        atomicAdd(&g_stats[statOff + tid], sCS[tid]);
        atomicAdd(&g_stats[statOff + 128 + tid], sCQ[tid]);
    }
}

// ---------------- final BN (elementwise) ----------------
__global__ void k_bnout(const float* x, int bnOff, const float* gam, const float* bet,
                        float* o, int nrows) {
    const float* mean = g_bnp + bnOff;
    const float* istd = g_bnp + bnOff + 128;
    int idx = blockIdx.x * blockDim.x + threadIdx.x;
    int stride = gridDim.x * blockDim.x;
    int total = nrows * 32;  // float4 units
    for (int i = idx; i < total; i += stride) {
        int c = (i & 31) << 2;
        float4 v = *(const float4*)(x + (size_t)i * 4);
        float4 r;
        r.x = (v.x - mean[c + 0]) * istd[c + 0] * gam[c + 0] + bet[c + 0];
        r.y = (v.y - mean[c + 1]) * istd[c + 1] * gam[c + 1] + bet[c + 1];
        r.z = (v.z - mean[c + 2]) * istd[c + 2] * gam[c + 2] + bet[c + 2];
        r.w = (v.w - mean[c + 3]) * istd[c + 3] * gam[c + 3] + bet[c + 3];
        *(float4*)(o + (size_t)i * 4) = r;
    }
}

// ---------------- launch ----------------
extern "C" void kernel_launch(void* const* d_in, const int* in_sizes, int n_in,
                              void* d_out, int out_size) {
    const float* h = (const float*)d_in[0];
    const float* e = (const float*)d_in[1];
    const int* src = (const int*)d_in[2];
    const int* dst = (const int*)d_in[3];
    const float* Wq = (const float*)d_in[4];
    const float* Wk = (const float*)d_in[5];
    const float* Wv = (const float*)d_in[6];
    const float* We = (const float*)d_in[7];
    const float* Wo_h = (const float*)d_in[8];
    const float* bo_h = (const float*)d_in[9];
    const float* Wo_e = (const float*)d_in[10];
    const float* bo_e = (const float*)d_in[11];
    const float* g1h = (const float*)d_in[12];
    const float* b1h = (const float*)d_in[13];
    const float* g1e = (const float*)d_in[14];
    const float* b1e = (const float*)d_in[15];
    const float* Wf1h = (const float*)d_in[16];
    const float* bf1h = (const float*)d_in[17];
    const float* Wf2h = (const float*)d_in[18];
    const float* bf2h = (const float*)d_in[19];
    const float* Wf1e = (const float*)d_in[20];
    const float* bf1e = (const float*)d_in[21];
    const float* Wf2e = (const float*)d_in[22];
    const float* bf2e = (const float*)d_in[23];
    const float* g2h = (const float*)d_in[24];
    const float* b2h = (const float*)d_in[25];
    const float* g2e = (const float*)d_in[26];
    const float* b2e = (const float*)d_in[27];
    float* out = (float*)d_out;
    float* out_e = out + (size_t)NN * D;

    float *p_hh, *p_h2, *p_ee, *p_tfw;
    cudaGetSymbolAddress((void**)&p_hh, g_hh);
    cudaGetSymbolAddress((void**)&p_h2, g_h2);
    cudaGetSymbolAddress((void**)&p_ee, g_ee);
    cudaGetSymbolAddress((void**)&p_tfw, g_tfw);

    const int smQ = (128 * 132 + 64 * 136) * 4;                              // ~100KB
    const int smN = (128 * 132 + 64 * 136 + 256) * 4;                        // ~101KB
    const int sm1 = (64 * 132 + 64 * 136 + 512 + 256 + 128) * 4;             // ~71.2KB
    const int smF = (128 * 132 + 5120 + 128 * 36 + 256) * 4;                 // 105KB
    cudaFuncSetAttribute(k_qkv, cudaFuncAttributeMaxDynamicSharedMemorySize, smQ);
    cudaFuncSetAttribute(k_nattn, cudaFuncAttributeMaxDynamicSharedMemorySize, smN);
    cudaFuncSetAttribute(k_edge1, cudaFuncAttributeMaxDynamicSharedMemorySize, sm1);
    cudaFuncSetAttribute(k_ffn, cudaFuncAttributeMaxDynamicSharedMemorySize, smF);

    const int NBLK = (NN + 127) / 128;  // 391

    k_zero<<<2048, 256>>>();
    k_prep<<<256, 256>>>(Wq, Wk, Wv, We, Wo_h, Wo_e, Wf1h, Wf2h, Wf1e, Wf2e);
    k_qkv<<<NBLK, 256, smQ>>>(h);
    k_edge1<<<NE / 64, 256, sm1>>>(e, src, dst, bo_e);
    k_nattn<<<NBLK, 256, smN>>>(h, bo_h);
    k_finalize<<<1, 128>>>(0, (float)NE, 0);      // bn1e
    k_finalize<<<1, 128>>>(256, (float)NN, 256);  // bn1h
    k_ffn<<<NE / 128, 256, smF>>>(p_ee, out_e, 0, g1e, b1e, p_tfw + T1E, bf1e, p_tfw + T2E, bf2e, 512, NE);
    k_ffn<<<NBLK, 256, smF>>>(p_hh, p_h2, 256, g1h, b1h, p_tfw + T1H, bf1h, p_tfw + T2H, bf2h, 768, NN);
    k_finalize<<<1, 128>>>(512, (float)NE, 512);  // bn2e
    k_finalize<<<1, 128>>>(768, (float)NN, 768);  // bn2h
    k_bnout<<<2960, 256>>>(p_h2, 768, g2h, b2h, out, NN);
    k_bnout<<<2960, 256>>>(out_e, 512, g2e, b2e, out_e, NE);
}